// round 1
// baseline (speedup 1.0000x reference)
#include <cuda_runtime.h>
#include <math.h>

#define L 8192
#define C 256
#define S 16
#define NCHUNK 32
#define TCH (L / NCHUNK)   // 256

// scratch (static device arrays — no allocation allowed)
__device__ float2 g_dtx[L * C];          // {dt, x}
__device__ float2 g_brc[L * S];          // {B/A, C}
__device__ float  g_Aagg[NCHUNK * C * S];
__device__ float  g_hagg[NCHUNK * C * S];
__device__ float  g_carry[NCHUNK * C * S];

__device__ __forceinline__ float softplus_f(float z) {
    // log(1+exp(z)), stable: max(z,0) + log1p(exp(-|z|))
    return fmaxf(z, 0.0f) + log1pf(__expf(-fabsf(z)));
}

// ---------------------------------------------------------------------------
// dt = softplus(0.01 + x @ W_dt + b_dt), packed with x into g_dtx.
// Classic 64x64x16 fp32 tiled GEMM, 256 threads, 4x4 microtile.
// ---------------------------------------------------------------------------
__global__ __launch_bounds__(256) void dt_gemm_kernel(
    const float* __restrict__ x, const float* __restrict__ Wdt,
    const float* __restrict__ bdt)
{
    __shared__ float As[16][68];   // [k][m], padded
    __shared__ float Bs[16][68];   // [k][n], padded

    const int tid = threadIdx.x;
    const int m0 = blockIdx.x * 64;
    const int n0 = blockIdx.y * 64;
    const int tr = tid >> 4;       // 0..15
    const int tc = tid & 15;       // 0..15

    // load mapping
    const int lm = tid >> 2;             // 0..63
    const int lk = (tid & 3) * 4;        // 0,4,8,12
    const int bk = tid >> 4;             // 0..15
    const int bn = (tid & 15) * 4;       // 0..60

    float acc[4][4] = {};

    for (int k0 = 0; k0 < 256; k0 += 16) {
        float4 av = *(const float4*)&x[(m0 + lm) * 256 + k0 + lk];
        As[lk + 0][lm] = av.x; As[lk + 1][lm] = av.y;
        As[lk + 2][lm] = av.z; As[lk + 3][lm] = av.w;
        *(float4*)&Bs[bk][bn] = *(const float4*)&Wdt[(k0 + bk) * 256 + n0 + bn];
        __syncthreads();
        #pragma unroll
        for (int k = 0; k < 16; k++) {
            float4 a = *(const float4*)&As[k][tr * 4];
            float4 b = *(const float4*)&Bs[k][tc * 4];
            acc[0][0] += a.x * b.x; acc[0][1] += a.x * b.y; acc[0][2] += a.x * b.z; acc[0][3] += a.x * b.w;
            acc[1][0] += a.y * b.x; acc[1][1] += a.y * b.y; acc[1][2] += a.y * b.z; acc[1][3] += a.y * b.w;
            acc[2][0] += a.z * b.x; acc[2][1] += a.z * b.y; acc[2][2] += a.z * b.z; acc[2][3] += a.z * b.w;
            acc[3][0] += a.w * b.x; acc[3][1] += a.w * b.y; acc[3][2] += a.w * b.z; acc[3][3] += a.w * b.w;
        }
        __syncthreads();
    }

    #pragma unroll
    for (int i = 0; i < 4; i++) {
        int m = m0 + tr * 4 + i;
        #pragma unroll
        for (int j = 0; j < 4; j++) {
            int n = n0 + tc * 4 + j;
            float dt = softplus_f(acc[i][j] + 0.01f + __ldg(&bdt[n]));
            g_dtx[m * C + n] = make_float2(dt, __ldg(&x[m * C + n]));
        }
    }
}

// ---------------------------------------------------------------------------
// B/A and C projections: g_brc[l][s] = { (1 + x@W_B + b_B)/A , x@W_C + b_C }
// One warp per row l; W_B|W_C staged in smem [256][32].
// ---------------------------------------------------------------------------
__global__ __launch_bounds__(256) void bc_kernel(
    const float* __restrict__ x,
    const float* __restrict__ WB, const float* __restrict__ bB,
    const float* __restrict__ WC, const float* __restrict__ bC,
    const float* __restrict__ logA)
{
    __shared__ float Ws[256][32];
    const int tid = threadIdx.x;
    for (int idx = tid; idx < 256 * 32; idx += 256) {
        int k = idx >> 5, j = idx & 31;
        Ws[k][j] = (j < 16) ? WB[k * 16 + j] : WC[k * 16 + (j - 16)];
    }
    __syncthreads();

    const int w = tid >> 5;
    const int j = tid & 31;
    const int l = blockIdx.x * 8 + w;
    const float4* x4 = (const float4*)(x + l * 256);

    float acc = 0.0f;
    #pragma unroll 8
    for (int k4 = 0; k4 < 64; k4++) {
        float4 v = __ldg(&x4[k4]);
        int k = k4 * 4;
        acc += v.x * Ws[k][j] + v.y * Ws[k + 1][j]
             + v.z * Ws[k + 2][j] + v.w * Ws[k + 3][j];
    }

    if (j < 16) {
        float A = -__expf(__ldg(&logA[j]));
        g_brc[l * S + j].x = (1.0f + acc + __ldg(&bB[j])) / A;
    } else {
        int s = j - 16;
        g_brc[l * S + s].y = acc + __ldg(&bC[s]);
    }
}

// ---------------------------------------------------------------------------
// Chunked scan. Warp layout: lane = csub*16 + s, warp owns 2 channels x 16 states.
// PASS==1: local scan from zero, emit (A_prod, h_local) per chunk.
// PASS==3: rerun with carry-in, contract over s via shfl, write y.
// ---------------------------------------------------------------------------
template<int PASS>
__global__ __launch_bounds__(128) void scan_kernel(
    const float* __restrict__ logA, float* __restrict__ y)
{
    const int lane = threadIdx.x & 31;
    const int w    = threadIdx.x >> 5;
    const int s    = lane & 15;
    const int csub = lane >> 4;
    const int c    = blockIdx.x * 8 + w * 2 + csub;
    const int chunk = blockIdx.y;
    const int l0 = chunk * TCH;
    const int csi = c * S + s;

    const float A = -__expf(__ldg(&logA[s]));

    float h, Ap;
    if (PASS == 1) { h = 0.0f; Ap = 1.0f; }
    else           { h = g_carry[chunk * (C * S) + csi]; Ap = 1.0f; }

    #pragma unroll 4
    for (int i = 0; i < TCH; i++) {
        const int l = l0 + i;
        float2 dx = __ldg(&g_dtx[l * C + c]);   // {dt, x}  (broadcast across 16 lanes)
        float2 bc = __ldg(&g_brc[l * S + s]);   // {B/A, C}
        float Ad = __expf(dx.x * A);
        float u  = __expf((Ad - 1.0f) * bc.x) * dx.y;
        h = fmaf(Ad, h, u);
        if (PASS == 1) {
            Ap *= Ad;
        } else {
            float t = bc.y * h;
            t += __shfl_xor_sync(0xffffffffu, t, 1);
            t += __shfl_xor_sync(0xffffffffu, t, 2);
            t += __shfl_xor_sync(0xffffffffu, t, 4);
            t += __shfl_xor_sync(0xffffffffu, t, 8);
            if (s == 0) y[l * C + c] = t;
        }
    }

    if (PASS == 1) {
        g_Aagg[chunk * (C * S) + csi] = Ap;
        g_hagg[chunk * (C * S) + csi] = h;
    }
}

// ---------------------------------------------------------------------------
// Cross-chunk carry scan: per (c,s), sequentially over 32 chunks.
// ---------------------------------------------------------------------------
__global__ __launch_bounds__(256) void carry_kernel()
{
    const int cs = blockIdx.x * 256 + threadIdx.x;   // 0..4095
    float carry = 0.0f;
    #pragma unroll
    for (int k = 0; k < NCHUNK; k++) {
        g_carry[k * (C * S) + cs] = carry;
        carry = fmaf(g_Aagg[k * (C * S) + cs], carry, g_hagg[k * (C * S) + cs]);
    }
}

extern "C" void kernel_launch(void* const* d_in, const int* in_sizes, int n_in,
                              void* d_out, int out_size)
{
    (void)in_sizes; (void)n_in; (void)out_size;
    const float* x    = (const float*)d_in[0];
    const float* logA = (const float*)d_in[1];
    const float* Wdt  = (const float*)d_in[2];
    const float* bdt  = (const float*)d_in[3];
    const float* WB   = (const float*)d_in[4];
    const float* bB   = (const float*)d_in[5];
    const float* WC   = (const float*)d_in[6];
    const float* bC   = (const float*)d_in[7];
    float* y = (float*)d_out;

    dt_gemm_kernel<<<dim3(L / 64, C / 64), 256>>>(x, Wdt, bdt);
    bc_kernel<<<L / 8, 256>>>(x, WB, bB, WC, bC, logA);
    scan_kernel<1><<<dim3(C / 8, NCHUNK), 128>>>(logA, y);
    carry_kernel<<<S * C / 256, 256>>>();
    scan_kernel<3><<<dim3(C / 8, NCHUNK), 128>>>(logA, y);
}

// round 2
// speedup vs baseline: 1.0028x; 1.0028x over previous
#include <cuda_runtime.h>
#include <math.h>

#define L 8192
#define C 256
#define S 16
#define NCHUNK 32
#define TCH (L / NCHUNK)   // 256

// scratch (static device arrays — no allocation allowed)
__device__ float2 g_dtx[L * C];          // {dt, x}
__device__ float2 g_brc[L * S];          // {B/A, C}
__device__ float  g_Aagg[NCHUNK * C * S];
__device__ float  g_hagg[NCHUNK * C * S];
__device__ float  g_carry[NCHUNK * C * S];

__device__ __forceinline__ float softplus_f(float z) {
    // log(1+exp(z)), stable: max(z,0) + log1p(exp(-|z|))
    return fmaxf(z, 0.0f) + log1pf(__expf(-fabsf(z)));
}

// ---------------------------------------------------------------------------
// dt = softplus(0.01 + x @ W_dt + b_dt), packed with x into g_dtx.
// Classic 64x64x16 fp32 tiled GEMM, 256 threads, 4x4 microtile.
// ---------------------------------------------------------------------------
__global__ __launch_bounds__(256) void dt_gemm_kernel(
    const float* __restrict__ x, const float* __restrict__ Wdt,
    const float* __restrict__ bdt)
{
    __shared__ float As[16][68];   // [k][m], padded
    __shared__ float Bs[16][68];   // [k][n], padded

    const int tid = threadIdx.x;
    const int m0 = blockIdx.x * 64;
    const int n0 = blockIdx.y * 64;
    const int tr = tid >> 4;       // 0..15
    const int tc = tid & 15;       // 0..15

    // load mapping
    const int lm = tid >> 2;             // 0..63
    const int lk = (tid & 3) * 4;        // 0,4,8,12
    const int bk = tid >> 4;             // 0..15
    const int bn = (tid & 15) * 4;       // 0..60

    float acc[4][4] = {};

    for (int k0 = 0; k0 < 256; k0 += 16) {
        float4 av = *(const float4*)&x[(m0 + lm) * 256 + k0 + lk];
        As[lk + 0][lm] = av.x; As[lk + 1][lm] = av.y;
        As[lk + 2][lm] = av.z; As[lk + 3][lm] = av.w;
        *(float4*)&Bs[bk][bn] = *(const float4*)&Wdt[(k0 + bk) * 256 + n0 + bn];
        __syncthreads();
        #pragma unroll
        for (int k = 0; k < 16; k++) {
            float4 a = *(const float4*)&As[k][tr * 4];
            float4 b = *(const float4*)&Bs[k][tc * 4];
            acc[0][0] += a.x * b.x; acc[0][1] += a.x * b.y; acc[0][2] += a.x * b.z; acc[0][3] += a.x * b.w;
            acc[1][0] += a.y * b.x; acc[1][1] += a.y * b.y; acc[1][2] += a.y * b.z; acc[1][3] += a.y * b.w;
            acc[2][0] += a.z * b.x; acc[2][1] += a.z * b.y; acc[2][2] += a.z * b.z; acc[2][3] += a.z * b.w;
            acc[3][0] += a.w * b.x; acc[3][1] += a.w * b.y; acc[3][2] += a.w * b.z; acc[3][3] += a.w * b.w;
        }
        __syncthreads();
    }

    #pragma unroll
    for (int i = 0; i < 4; i++) {
        int m = m0 + tr * 4 + i;
        #pragma unroll
        for (int j = 0; j < 4; j++) {
            int n = n0 + tc * 4 + j;
            float dt = softplus_f(acc[i][j] + 0.01f + __ldg(&bdt[n]));
            g_dtx[m * C + n] = make_float2(dt, __ldg(&x[m * C + n]));
        }
    }
}

// ---------------------------------------------------------------------------
// B/A and C projections: g_brc[l][s] = { (1 + x@W_B + b_B)/A , x@W_C + b_C }
// One warp per row l; W_B|W_C staged in smem [256][32].
// ---------------------------------------------------------------------------
__global__ __launch_bounds__(256) void bc_kernel(
    const float* __restrict__ x,
    const float* __restrict__ WB, const float* __restrict__ bB,
    const float* __restrict__ WC, const float* __restrict__ bC,
    const float* __restrict__ logA)
{
    __shared__ float Ws[256][32];
    const int tid = threadIdx.x;
    for (int idx = tid; idx < 256 * 32; idx += 256) {
        int k = idx >> 5, j = idx & 31;
        Ws[k][j] = (j < 16) ? WB[k * 16 + j] : WC[k * 16 + (j - 16)];
    }
    __syncthreads();

    const int w = tid >> 5;
    const int j = tid & 31;
    const int l = blockIdx.x * 8 + w;
    const float4* x4 = (const float4*)(x + l * 256);

    float acc = 0.0f;
    #pragma unroll 8
    for (int k4 = 0; k4 < 64; k4++) {
        float4 v = __ldg(&x4[k4]);
        int k = k4 * 4;
        acc += v.x * Ws[k][j] + v.y * Ws[k + 1][j]
             + v.z * Ws[k + 2][j] + v.w * Ws[k + 3][j];
    }

    if (j < 16) {
        float A = -__expf(__ldg(&logA[j]));
        g_brc[l * S + j].x = (1.0f + acc + __ldg(&bB[j])) / A;
    } else {
        int s = j - 16;
        g_brc[l * S + s].y = acc + __ldg(&bC[s]);
    }
}

// ---------------------------------------------------------------------------
// Chunked scan. Warp layout: lane = csub*16 + s, warp owns 2 channels x 16 states.
// PASS==1: local scan from zero, emit (A_prod, h_local) per chunk.
// PASS==3: rerun with carry-in, contract over s via shfl, write y.
// ---------------------------------------------------------------------------
template<int PASS>
__global__ __launch_bounds__(128) void scan_kernel(
    const float* __restrict__ logA, float* __restrict__ y)
{
    const int lane = threadIdx.x & 31;
    const int w    = threadIdx.x >> 5;
    const int s    = lane & 15;
    const int csub = lane >> 4;
    const int c    = blockIdx.x * 8 + w * 2 + csub;
    const int chunk = blockIdx.y;
    const int l0 = chunk * TCH;
    const int csi = c * S + s;

    const float A = -__expf(__ldg(&logA[s]));

    float h, Ap;
    if (PASS == 1) { h = 0.0f; Ap = 1.0f; }
    else           { h = g_carry[chunk * (C * S) + csi]; Ap = 1.0f; }

    #pragma unroll 4
    for (int i = 0; i < TCH; i++) {
        const int l = l0 + i;
        float2 dx = __ldg(&g_dtx[l * C + c]);   // {dt, x}  (broadcast across 16 lanes)
        float2 bc = __ldg(&g_brc[l * S + s]);   // {B/A, C}
        float Ad = __expf(dx.x * A);
        float u  = __expf((Ad - 1.0f) * bc.x) * dx.y;
        h = fmaf(Ad, h, u);
        if (PASS == 1) {
            Ap *= Ad;
        } else {
            float t = bc.y * h;
            t += __shfl_xor_sync(0xffffffffu, t, 1);
            t += __shfl_xor_sync(0xffffffffu, t, 2);
            t += __shfl_xor_sync(0xffffffffu, t, 4);
            t += __shfl_xor_sync(0xffffffffu, t, 8);
            if (s == 0) y[l * C + c] = t;
        }
    }

    if (PASS == 1) {
        g_Aagg[chunk * (C * S) + csi] = Ap;
        g_hagg[chunk * (C * S) + csi] = h;
    }
}

// ---------------------------------------------------------------------------
// Cross-chunk carry scan: per (c,s), sequentially over 32 chunks.
// ---------------------------------------------------------------------------
__global__ __launch_bounds__(256) void carry_kernel()
{
    const int cs = blockIdx.x * 256 + threadIdx.x;   // 0..4095
    float carry = 0.0f;
    #pragma unroll
    for (int k = 0; k < NCHUNK; k++) {
        g_carry[k * (C * S) + cs] = carry;
        carry = fmaf(g_Aagg[k * (C * S) + cs], carry, g_hagg[k * (C * S) + cs]);
    }
}

extern "C" void kernel_launch(void* const* d_in, const int* in_sizes, int n_in,
                              void* d_out, int out_size)
{
    (void)in_sizes; (void)n_in; (void)out_size;
    const float* x    = (const float*)d_in[0];
    const float* logA = (const float*)d_in[1];
    const float* Wdt  = (const float*)d_in[2];
    const float* bdt  = (const float*)d_in[3];
    const float* WB   = (const float*)d_in[4];
    const float* bB   = (const float*)d_in[5];
    const float* WC   = (const float*)d_in[6];
    const float* bC   = (const float*)d_in[7];
    float* y = (float*)d_out;

    dt_gemm_kernel<<<dim3(L / 64, C / 64), 256>>>(x, Wdt, bdt);
    bc_kernel<<<L / 8, 256>>>(x, WB, bB, WC, bC, logA);
    scan_kernel<1><<<dim3(C / 8, NCHUNK), 128>>>(logA, y);
    carry_kernel<<<S * C / 256, 256>>>();
    scan_kernel<3><<<dim3(C / 8, NCHUNK), 128>>>(logA, y);
}